// round 14
// baseline (speedup 1.0000x reference)
#include <cuda_runtime.h>
#include <cuda.h>
#include <cuda_bf16.h>
#include <math.h>
#include <stdint.h>

// ---------------- problem constants ----------------
#define BATCH     4
#define SEQ       512
#define NTOK      (BATCH*SEQ)          // 2048
#define STATE     510
#define D_MODEL   1024
#define D_INNER   2048
#define D_STATE   128
#define NHEADS    32
#define HEADDIM   64
#define DCONV     4
#define CONV_DIM  (D_INNER + 2*D_STATE)            // 2304
#define D_IN_PROJ (2*D_INNER + 2*D_STATE + NHEADS) // 4384
#define NBLOCKS   4

// ---------------- scratch (device globals, no allocs) ----------------
__device__ float g_tmp [NTOK * D_MODEL];
__device__ float g_h   [NTOK * D_MODEL];
__device__ float g_z   [NTOK * D_IN_PROJ];
__device__ float g_conv[NTOK * CONV_DIM];
__device__ float g_dt  [NTOK * NHEADS];
__device__ float g_dA  [NTOK * NHEADS];
__device__ float g_y   [NTOK * D_INNER];

// bf16 hi/lo operand buffers (16B aligned for cp.async)
__device__ __align__(16) __nv_bfloat16 g_cat_h[NTOK * 512];
__device__ __align__(16) __nv_bfloat16 g_cat_l[NTOK * 512];
__device__ __align__(16) __nv_bfloat16 g_tmp_h[NTOK * D_MODEL];
__device__ __align__(16) __nv_bfloat16 g_tmp_l[NTOK * D_MODEL];
__device__ __align__(16) __nv_bfloat16 g_h_h  [NTOK * D_MODEL];
__device__ __align__(16) __nv_bfloat16 g_h_l  [NTOK * D_MODEL];
__device__ __align__(16) __nv_bfloat16 g_yn_h [NTOK * D_INNER];
__device__ __align__(16) __nv_bfloat16 g_yn_l [NTOK * D_INNER];
// transposed weight scratch (max: Win^T = 4384 x 1024)
__device__ __align__(16) __nv_bfloat16 g_wth[D_IN_PROJ * D_MODEL];
__device__ __align__(16) __nv_bfloat16 g_wtl[D_IN_PROJ * D_MODEL];

// ================= helpers =================
__device__ __forceinline__ uint32_t smem_to_u32(const void* p) {
    uint32_t a;
    asm("{ .reg .u64 t; cvta.to.shared.u64 t, %1; cvt.u32.u64 %0, t; }" : "=r"(a) : "l"(p));
    return a;
}
#define LDSM_X4(r0, r1, r2, r3, addr) \
    asm volatile("ldmatrix.sync.aligned.m8n8.x4.shared.b16 {%0,%1,%2,%3}, [%4];" \
        : "=r"(r0), "=r"(r1), "=r"(r2), "=r"(r3) : "r"(addr))
#define CP_ASYNC16(dst, src) \
    asm volatile("cp.async.ca.shared.global [%0], [%1], 16;" :: "r"(dst), "l"(src) : "memory")
#define CP_ASYNC4(dst, src) \
    asm volatile("cp.async.ca.shared.global [%0], [%1], 4;" :: "r"(dst), "l"(src) : "memory")
#define CP_COMMIT() asm volatile("cp.async.commit_group;" ::: "memory")
#define CP_WAIT1()  asm volatile("cp.async.wait_group 1;" ::: "memory")
#define CP_WAIT0()  asm volatile("cp.async.wait_group 0;" ::: "memory")

// Split x0,x1 into packed bf16x2 hi and lo parts (hi half of reg = x1).
__device__ __forceinline__ void bf16x2split(float x0, float x1, uint32_t& hi, uint32_t& lo) {
    uint32_t h;
    asm("cvt.rn.bf16x2.f32 %0, %1, %2;" : "=r"(h) : "f"(x1), "f"(x0));
    float h0 = __uint_as_float(h << 16);
    float h1 = __uint_as_float(h & 0xffff0000u);
    float l0 = x0 - h0;
    float l1 = x1 - h1;
    hi = h;
    asm("cvt.rn.bf16x2.f32 %0, %1, %2;" : "=r"(lo) : "f"(l1), "f"(l0));
}

#define MMA_BF16(cr, a, b) \
    asm volatile("mma.sync.aligned.m16n8k16.row.col.f32.bf16.bf16.f32 " \
        "{%0,%1,%2,%3},{%4,%5,%6,%7},{%8,%9},{%0,%1,%2,%3};" \
        : "+f"((cr)[0]), "+f"((cr)[1]), "+f"((cr)[2]), "+f"((cr)[3]) \
        : "r"((a)[0]), "r"((a)[1]), "r"((a)[2]), "r"((a)[3]), \
          "r"((b)[0]), "r"((b)[1]))

// ================= weight split+transpose: W[K,N] -> Th/Tl[N,K] bf16 =================
__global__ __launch_bounds__(256)
void wsplit_t(const float* __restrict__ W, __nv_bfloat16* __restrict__ Th,
              __nv_bfloat16* __restrict__ Tl, int K, int N)
{
    __shared__ float t[32][33];
    int n0 = blockIdx.x * 32, k0 = blockIdx.y * 32;
    int tx = threadIdx.x, ty = threadIdx.y;   // 32 x 8
    #pragma unroll
    for (int i = 0; i < 32; i += 8)
        t[ty + i][tx] = W[(size_t)(k0 + ty + i) * N + n0 + tx];
    __syncthreads();
    #pragma unroll
    for (int i = 0; i < 32; i += 8) {
        int n = n0 + ty + i, k = k0 + tx;
        float v = t[tx][ty + i];
        __nv_bfloat16 h = __float2bfloat16(v);
        Th[(size_t)n * K + k] = h;
        Tl[(size_t)n * K + k] = __float2bfloat16(v - __bfloat162float(h));
    }
}

// ================= bf16x3 GEMM, pre-split operands, ldmatrix fragments =================
#define STAGE_BYTES 40960
#define GEMM_SMEM_BYTES (2 * STAGE_BYTES)

template<int BIAS, int RELU, int WSPLIT>
__global__ __launch_bounds__(256, 2)
void gemm_bf3(const __nv_bfloat16* __restrict__ Ah, const __nv_bfloat16* __restrict__ Al,
              const __nv_bfloat16* __restrict__ Bh, const __nv_bfloat16* __restrict__ Bl,
              const float* __restrict__ bias, float* __restrict__ C,
              __nv_bfloat16* __restrict__ Ch, __nv_bfloat16* __restrict__ Cl,
              int M, int N, int K)
{
    extern __shared__ char smc[];
    const uint32_t sb = smem_to_u32(smc);

    const int tid = threadIdx.x, lane = tid & 31, w = tid >> 5;
    const int wm = w >> 2, wn = w & 3;          // warp grid 2(m) x 4(n)
    const int grp = lane >> 2, kq = lane & 3;
    const int m0 = blockIdx.y * 128, n0 = blockIdx.x * 128;

    const int r = tid >> 2, q = tid & 3;        // cp.async: row 0..63, 16B chunk 0..3

    // ldmatrix lane-address components
    const uint32_t laneA = (uint32_t)((lane & 15) * 80 + (lane >> 4) * 16);
    const uint32_t laneB = (uint32_t)((((lane >> 4) & 1) * 8 + (lane & 7)) * 80
                                      + ((lane >> 3) & 1) * 16);
    const uint32_t aWarp = (uint32_t)(wm * 64 * 80);
    const uint32_t bWarp = (uint32_t)(wn * 32 * 80);

    float c[4][4][4];
    #pragma unroll
    for (int i = 0; i < 4; i++)
        #pragma unroll
        for (int j = 0; j < 4; j++)
            #pragma unroll
            for (int p = 0; p < 4; p++) c[i][j][p] = 0.f;

    const int nch = K >> 5;

    int br0 = n0 + r;       if (br0 >= N) br0 = N - 1;
    int br1 = n0 + r + 64;  if (br1 >= N) br1 = N - 1;

    auto issue = [&](int ch) {
        const uint32_t st = sb + (uint32_t)(ch & 1) * STAGE_BYTES;
        const int k0 = ch << 5;
        const size_t aoff = (size_t)(m0 + r) * K + k0 + q * 8;
        CP_ASYNC16(st + (uint32_t)(r * 80 + q * 16),                 Ah + aoff);
        CP_ASYNC16(st + (uint32_t)((r + 64) * 80 + q * 16),          Ah + aoff + (size_t)64 * K);
        CP_ASYNC16(st + 10240u + (uint32_t)(r * 80 + q * 16),        Al + aoff);
        CP_ASYNC16(st + 10240u + (uint32_t)((r + 64) * 80 + q * 16), Al + aoff + (size_t)64 * K);
        const size_t b0off = (size_t)br0 * K + k0 + q * 8;
        const size_t b1off = (size_t)br1 * K + k0 + q * 8;
        CP_ASYNC16(st + 20480u + (uint32_t)(r * 80 + q * 16),        Bh + b0off);
        CP_ASYNC16(st + 20480u + (uint32_t)((r + 64) * 80 + q * 16), Bh + b1off);
        CP_ASYNC16(st + 30720u + (uint32_t)(r * 80 + q * 16),        Bl + b0off);
        CP_ASYNC16(st + 30720u + (uint32_t)((r + 64) * 80 + q * 16), Bl + b1off);
        CP_COMMIT();
    };

    issue(0);

    for (int ch = 0; ch < nch; ch++) {
        if (ch + 1 < nch) { issue(ch + 1); CP_WAIT1(); }
        else              { CP_WAIT0(); }
        __syncthreads();

        const uint32_t st = sb + (uint32_t)(ch & 1) * STAGE_BYTES;

        #pragma unroll
        for (int ks = 0; ks < 2; ks++) {
            const uint32_t ko = (uint32_t)(ks * 32);
            uint32_t bh[4][2], bl[4][2];
            #pragma unroll
            for (int pa = 0; pa < 2; pa++) {
                uint32_t ba = st + 20480u + bWarp + (uint32_t)(pa * 16 * 80) + laneB + ko;
                LDSM_X4(bh[2*pa][0], bh[2*pa][1], bh[2*pa+1][0], bh[2*pa+1][1], ba);
                uint32_t bla = ba + 10240u;
                LDSM_X4(bl[2*pa][0], bl[2*pa][1], bl[2*pa+1][0], bl[2*pa+1][1], bla);
            }
            #pragma unroll
            for (int ma = 0; ma < 4; ma++) {
                uint32_t aa = st + aWarp + (uint32_t)(ma * 16 * 80) + laneA + ko;
                uint32_t ah[4], al[4];
                LDSM_X4(ah[0], ah[1], ah[2], ah[3], aa);
                LDSM_X4(al[0], al[1], al[2], al[3], aa + 10240u);
                #pragma unroll
                for (int na = 0; na < 4; na++) {
                    MMA_BF16(c[ma][na], ah, bh[na]);
                    MMA_BF16(c[ma][na], ah, bl[na]);
                    MMA_BF16(c[ma][na], al, bh[na]);
                }
            }
        }
        __syncthreads();
    }

    // ---- epilogue ----
    #pragma unroll
    for (int ma = 0; ma < 4; ma++) {
        int row = m0 + wm * 64 + ma * 16 + grp;
        #pragma unroll
        for (int na = 0; na < 4; na++) {
            int col = n0 + wn * 32 + na * 8 + kq * 2;
            if (col < N) {
                float b0 = 0.f, b1 = 0.f;
                if (BIAS) { b0 = bias[col]; b1 = bias[col + 1]; }
                float v0 = c[ma][na][0] + b0, v1 = c[ma][na][1] + b1;
                float v2 = c[ma][na][2] + b0, v3 = c[ma][na][3] + b1;
                if (RELU) {
                    v0 = fmaxf(v0, 0.f); v1 = fmaxf(v1, 0.f);
                    v2 = fmaxf(v2, 0.f); v3 = fmaxf(v3, 0.f);
                }
                *(float2*)(C + (size_t)row * N + col)       = make_float2(v0, v1);
                *(float2*)(C + (size_t)(row + 8) * N + col) = make_float2(v2, v3);
                if (WSPLIT) {
                    uint32_t h01, l01, h23, l23;
                    bf16x2split(v0, v1, h01, l01);
                    bf16x2split(v2, v3, h23, l23);
                    *(uint32_t*)(Ch + (size_t)row * N + col)       = h01;
                    *(uint32_t*)(Cl + (size_t)row * N + col)       = l01;
                    *(uint32_t*)(Ch + (size_t)(row + 8) * N + col) = h23;
                    *(uint32_t*)(Cl + (size_t)(row + 8) * N + col) = l23;
                }
            }
        }
    }
}

// ---------------- helpers ----------------
__device__ __forceinline__ float siluf(float v) { return v / (1.f + expf(-v)); }

__device__ __forceinline__ float blockReduceSum256(float v) {
    __shared__ float s[8];
    __shared__ float tot;
    int lane = threadIdx.x & 31, w = threadIdx.x >> 5;
    #pragma unroll
    for (int o = 16; o; o >>= 1) v += __shfl_xor_sync(0xffffffffu, v, o);
    if (lane == 0) s[w] = v;
    __syncthreads();
    if (threadIdx.x < 32) {
        float t = (threadIdx.x < 8) ? s[threadIdx.x] : 0.f;
        #pragma unroll
        for (int o = 4; o; o >>= 1) t += __shfl_xor_sync(0xffffffffu, t, o);
        if (threadIdx.x == 0) tot = t;
    }
    __syncthreads();
    return tot;
}

// ---------------- elementwise kernels ----------------
__global__ void concat_kernel(const float* __restrict__ x, const float* __restrict__ sl,
                              const float* __restrict__ cr,
                              __nv_bfloat16* __restrict__ oh, __nv_bfloat16* __restrict__ ol)
{
    int idx = blockIdx.x * blockDim.x + threadIdx.x;   // NTOK*512
    int c = idx & 511, r = idx >> 9;
    float v;
    if (c < STATE)      v = x[(size_t)r * STATE + c];
    else if (c == STATE) v = sl[r];
    else                 v = cr[r];
    __nv_bfloat16 h = __float2bfloat16(v);
    oh[idx] = h;
    ol[idx] = __float2bfloat16(v - __bfloat162float(h));
}

__global__ void conv_silu_kernel(const float* __restrict__ zb, const float* __restrict__ cw,
                                 const float* __restrict__ cb, float* __restrict__ out)
{
    int idx = blockIdx.x * blockDim.x + threadIdx.x;   // NTOK*CONV_DIM
    if (idx >= NTOK * CONV_DIM) return;
    int ch = idx % CONV_DIM;
    int t  = idx / CONV_DIM;
    int l = t & (SEQ - 1), b = t >> 9;
    float s = cb[ch];
    #pragma unroll
    for (int k = 0; k < DCONV; k++) {
        int ll = l - (DCONV - 1) + k;
        if (ll >= 0)
            s = fmaf(zb[((size_t)(b * SEQ + ll)) * D_IN_PROJ + D_INNER + ch], cw[ch * DCONV + k], s);
    }
    out[idx] = siluf(s);
}

__global__ void dt_kernel(const float* __restrict__ zb, const float* __restrict__ dtb,
                          const float* __restrict__ Alog,
                          float* __restrict__ dt, float* __restrict__ dA)
{
    int idx = blockIdx.x * blockDim.x + threadIdx.x;   // NTOK*NHEADS
    if (idx >= NTOK * NHEADS) return;
    int hh = idx & (NHEADS - 1), row = idx >> 5;
    float v = zb[(size_t)row * D_IN_PROJ + (D_INNER + CONV_DIM) + hh] + dtb[hh];
    float sp = (v > 20.f) ? v : log1pf(expf(v));
    float a = -expf(Alog[hh]);
    dt[idx] = sp;
    dA[idx] = expf(sp * a);
}

// ---------------- selective scan: 1 CTA per (b, head), 512 threads ----------------
#define SCHUNK 16
#define NCHUNK (SEQ / SCHUNK)

__global__ __launch_bounds__(512)
void scan_kernel(const float* __restrict__ conv, const float* __restrict__ dt,
                 const float* __restrict__ dA, const float* __restrict__ Dsk,
                 float* __restrict__ y)
{
    __shared__ float sB[2][SCHUNK][D_STATE];
    __shared__ float sC[2][SCHUNK][D_STATE];
    __shared__ float sX[2][SCHUNK][HEADDIM];
    __shared__ float sdt[2][SCHUNK];
    __shared__ float sda[2][SCHUNK];

    int bh = blockIdx.x;
    int b = bh >> 5, hh = bh & 31;
    int tid = threadIdx.x;
    int p = tid >> 3, nq = tid & 7;

    const size_t convb = (size_t)b * SEQ * CONV_DIM;
    const uint32_t sBa = smem_to_u32(&sB[0][0][0]);
    const uint32_t sCa = smem_to_u32(&sC[0][0][0]);
    const uint32_t sXa = smem_to_u32(&sX[0][0][0]);
    const uint32_t sdta = smem_to_u32(&sdt[0][0]);
    const uint32_t sdaa = smem_to_u32(&sda[0][0]);

    auto issue = [&](int ch) {
        const int l0 = ch * SCHUNK;
        const int buf = ch & 1;
        {
            int st = tid >> 5, f4 = tid & 31;
            const float* src = conv + convb + (size_t)(l0 + st) * CONV_DIM + D_INNER + f4 * 4;
            CP_ASYNC16(sBa + (uint32_t)(buf * SCHUNK * D_STATE + st * D_STATE + f4 * 4) * 4u, src);
        }
        {
            int st = tid >> 5, f4 = tid & 31;
            const float* src = conv + convb + (size_t)(l0 + st) * CONV_DIM + D_INNER + D_STATE + f4 * 4;
            CP_ASYNC16(sCa + (uint32_t)(buf * SCHUNK * D_STATE + st * D_STATE + f4 * 4) * 4u, src);
        }
        if (tid < 256) {
            int st = tid >> 4, f4 = tid & 15;
            const float* src = conv + convb + (size_t)(l0 + st) * CONV_DIM + hh * HEADDIM + f4 * 4;
            CP_ASYNC16(sXa + (uint32_t)(buf * SCHUNK * HEADDIM + st * HEADDIM + f4 * 4) * 4u, src);
        } else if (tid < 272) {
            int s = tid - 256;
            CP_ASYNC4(sdta + (uint32_t)(buf * SCHUNK + s) * 4u,
                      dt + (size_t)(b * SEQ + l0 + s) * NHEADS + hh);
        } else if (tid < 288) {
            int s = tid - 272;
            CP_ASYNC4(sdaa + (uint32_t)(buf * SCHUNK + s) * 4u,
                      dA + (size_t)(b * SEQ + l0 + s) * NHEADS + hh);
        }
        CP_COMMIT();
    };

    float hs[16];
    #pragma unroll
    for (int i = 0; i < 16; i++) hs[i] = 0.f;
    float dsk = Dsk[hh];

    issue(0);

    for (int ch = 0; ch < NCHUNK; ch++) {
        if (ch + 1 < NCHUNK) { issue(ch + 1); CP_WAIT1(); }
        else                 { CP_WAIT0(); }
        __syncthreads();
        const int buf = ch & 1;

        #pragma unroll 2
        for (int s = 0; s < SCHUNK; s++) {
            int l = ch * SCHUNK + s;
            float dtv = sdt[buf][s];
            float dav = sda[buf][s];
            float xp = sX[buf][s][p];
            float coef = dtv * xp;
            const float4* B4 = (const float4*)&sB[buf][s][nq * 16];
            const float4* C4 = (const float4*)&sC[buf][s][nq * 16];
            float4 bv0 = B4[0], bv1 = B4[1], bv2 = B4[2], bv3 = B4[3];
            float4 cv0 = C4[0], cv1 = C4[1], cv2 = C4[2], cv3 = C4[3];
            hs[0]  = fmaf(hs[0],  dav, coef * bv0.x);
            hs[1]  = fmaf(hs[1],  dav, coef * bv0.y);
            hs[2]  = fmaf(hs[2],  dav, coef * bv0.z);
            hs[3]  = fmaf(hs[3],  dav, coef * bv0.w);
            hs[4]  = fmaf(hs[4],  dav, coef * bv1.x);
            hs[5]  = fmaf(hs[5],  dav, coef * bv1.y);
            hs[6]  = fmaf(hs[6],  dav, coef * bv1.z);
            hs[7]  = fmaf(hs[7],  dav, coef * bv1.w);
            hs[8]  = fmaf(hs[8],  dav, coef * bv2.x);
            hs[9]  = fmaf(hs[9],  dav, coef * bv2.y);
            hs[10] = fmaf(hs[10], dav, coef * bv2.z);
            hs[11] = fmaf(hs[11], dav, coef * bv2.w);
            hs[12] = fmaf(hs[12], dav, coef * bv3.x);
            hs[13] = fmaf(hs[13], dav, coef * bv3.y);
            hs[14] = fmaf(hs[14], dav, coef * bv3.z);
            hs[15] = fmaf(hs[15], dav, coef * bv3.w);
            float a0 = hs[0] * cv0.x;
            float a1 = hs[1] * cv0.y;
            float a2 = hs[2] * cv0.z;
            float a3 = hs[3] * cv0.w;
            a0 = fmaf(hs[4],  cv1.x, a0);
            a1 = fmaf(hs[5],  cv1.y, a1);
            a2 = fmaf(hs[6],  cv1.z, a2);
            a3 = fmaf(hs[7],  cv1.w, a3);
            a0 = fmaf(hs[8],  cv2.x, a0);
            a1 = fmaf(hs[9],  cv2.y, a1);
            a2 = fmaf(hs[10], cv2.z, a2);
            a3 = fmaf(hs[11], cv2.w, a3);
            a0 = fmaf(hs[12], cv3.x, a0);
            a1 = fmaf(hs[13], cv3.y, a1);
            a2 = fmaf(hs[14], cv3.z, a2);
            a3 = fmaf(hs[15], cv3.w, a3);
            float acc = (a0 + a1) + (a2 + a3);
            acc += __shfl_xor_sync(0xffffffffu, acc, 1);
            acc += __shfl_xor_sync(0xffffffffu, acc, 2);
            acc += __shfl_xor_sync(0xffffffffu, acc, 4);
            if (nq == 0)
                y[((size_t)(b * SEQ + l)) * D_INNER + hh * HEADDIM + p] = acc + dsk * xp;
        }
        __syncthreads();
    }
}

// ---------------- gated RMSNorm (writes bf16 hi/lo for next GEMM) ----------------
__global__ __launch_bounds__(256)
void gated_norm_kernel(const float* __restrict__ y, const float* __restrict__ z,
                       const float* __restrict__ nw,
                       __nv_bfloat16* __restrict__ oh, __nv_bfloat16* __restrict__ ol)
{
    int r = blockIdx.x;
    float g[8];
    float ss = 0.f;
    #pragma unroll
    for (int j = 0; j < 8; j++) {
        int c = j * 256 + threadIdx.x;
        float zv = z[(size_t)r * D_IN_PROJ + c];
        float gv = y[(size_t)r * D_INNER + c] * siluf(zv);
        g[j] = gv;
        ss = fmaf(gv, gv, ss);
    }
    ss = blockReduceSum256(ss);
    float inv = rsqrtf(ss / (float)D_INNER + 1e-5f);
    #pragma unroll
    for (int j = 0; j < 8; j++) {
        int c = j * 256 + threadIdx.x;
        float v = g[j] * inv * nw[c];
        __nv_bfloat16 h = __float2bfloat16(v);
        oh[(size_t)r * D_INNER + c] = h;
        ol[(size_t)r * D_INNER + c] = __float2bfloat16(v - __bfloat162float(h));
    }
}

// ---------------- final N=1 projection ----------------
__global__ __launch_bounds__(256)
void dot_kernel(const float* __restrict__ t, const float* __restrict__ w,
                const float* __restrict__ b, float* __restrict__ out)
{
    int r = blockIdx.x;
    float s = 0.f;
    for (int k = threadIdx.x; k < D_MODEL; k += 256)
        s = fmaf(t[(size_t)r * D_MODEL + k], w[k], s);
    s = blockReduceSum256(s);
    if (threadIdx.x == 0) out[r] = s + b[0];
}

// ---------------- launch ----------------
extern "C" void kernel_launch(void* const* d_in, const int* in_sizes, int n_in,
                              void* d_out, int out_size)
{
    const float* x    = (const float*)d_in[0];
    const float* sl   = (const float*)d_in[1];
    const float* cr   = (const float*)d_in[2];
    const float* iw1  = (const float*)d_in[3];
    const float* ib1  = (const float*)d_in[4];
    const float* iw2  = (const float*)d_in[5];
    const float* ib2  = (const float*)d_in[6];
    const float* Win  = (const float*)d_in[7];
    const float* cw   = (const float*)d_in[8];
    const float* cb   = (const float*)d_in[9];
    const float* dtb  = (const float*)d_in[10];
    const float* Alog = (const float*)d_in[11];
    const float* Dsk  = (const float*)d_in[12];
    const float* nw   = (const float*)d_in[13];
    const float* Wout = (const float*)d_in[14];
    const float* ow1  = (const float*)d_in[15];
    const float* ob1  = (const float*)d_in[16];
    const float* ow2  = (const float*)d_in[17];
    const float* ob2  = (const float*)d_in[18];
    float* out = (float*)d_out;

    float *tmp, *h, *z, *conv, *dt, *dA, *y;
    __nv_bfloat16 *cath, *catl, *tmph, *tmpl, *hh_, *hl_, *ynh, *ynl, *wth, *wtl;
    cudaGetSymbolAddress((void**)&tmp,  g_tmp);
    cudaGetSymbolAddress((void**)&h,    g_h);
    cudaGetSymbolAddress((void**)&z,    g_z);
    cudaGetSymbolAddress((void**)&conv, g_conv);
    cudaGetSymbolAddress((void**)&dt,   g_dt);
    cudaGetSymbolAddress((void**)&dA,   g_dA);
    cudaGetSymbolAddress((void**)&y,    g_y);
    cudaGetSymbolAddress((void**)&cath, g_cat_h);
    cudaGetSymbolAddress((void**)&catl, g_cat_l);
    cudaGetSymbolAddress((void**)&tmph, g_tmp_h);
    cudaGetSymbolAddress((void**)&tmpl, g_tmp_l);
    cudaGetSymbolAddress((void**)&hh_,  g_h_h);
    cudaGetSymbolAddress((void**)&hl_,  g_h_l);
    cudaGetSymbolAddress((void**)&ynh,  g_yn_h);
    cudaGetSymbolAddress((void**)&ynl,  g_yn_l);
    cudaGetSymbolAddress((void**)&wth,  g_wth);
    cudaGetSymbolAddress((void**)&wtl,  g_wtl);

    cudaFuncSetAttribute(gemm_bf3<1,1,1>, cudaFuncAttributeMaxDynamicSharedMemorySize, GEMM_SMEM_BYTES);
    cudaFuncSetAttribute(gemm_bf3<1,0,1>, cudaFuncAttributeMaxDynamicSharedMemorySize, GEMM_SMEM_BYTES);
    cudaFuncSetAttribute(gemm_bf3<0,0,0>, cudaFuncAttributeMaxDynamicSharedMemorySize, GEMM_SMEM_BYTES);
    cudaFuncSetAttribute(gemm_bf3<0,0,1>, cudaFuncAttributeMaxDynamicSharedMemorySize, GEMM_SMEM_BYTES);
    cudaFuncSetAttribute(gemm_bf3<1,1,0>, cudaFuncAttributeMaxDynamicSharedMemorySize, GEMM_SMEM_BYTES);

    const int MT = NTOK / 128;   // 16 M-tiles
    dim3 wsb(32, 8);

    // ---- input MLP (wsplits hoisted so launch index 3 = gemm_bf3 for ncu) ----
    wsplit_t<<<dim3(512/32, 512/32), wsb>>>(iw1, wth, wtl, 512, 512);                 // 0
    // second weight uses a distinct region: pack iw2^T after iw1^T in the big buffer
    __nv_bfloat16* wth2 = wth + (size_t)512 * 512;
    __nv_bfloat16* wtl2 = wtl + (size_t)512 * 512;
    wsplit_t<<<dim3(D_MODEL/32, 512/32), wsb>>>(iw2, wth2, wtl2, 512, D_MODEL);       // 1
    concat_kernel<<<NTOK * 512 / 256, 256>>>(x, sl, cr, cath, catl);                  // 2
    gemm_bf3<1,1,1><<<dim3(512/128, MT), 256, GEMM_SMEM_BYTES>>>(                     // 3 <- profiled
        cath, catl, wth, wtl, ib1, tmp, tmph, tmpl, NTOK, 512, 512);
    gemm_bf3<1,0,1><<<dim3(D_MODEL/128, MT), 256, GEMM_SMEM_BYTES>>>(
        tmph, tmpl, wth2, wtl2, ib2, h, hh_, hl_, NTOK, D_MODEL, 512);

    for (int i = 0; i < NBLOCKS; i++) {
        wsplit_t<<<dim3(D_IN_PROJ/32, D_MODEL/32), wsb>>>(
            Win + (size_t)i * D_MODEL * D_IN_PROJ, wth, wtl, D_MODEL, D_IN_PROJ);
        gemm_bf3<0,0,0><<<dim3((D_IN_PROJ + 127)/128, MT), 256, GEMM_SMEM_BYTES>>>(
            hh_, hl_, wth, wtl, nullptr, z, nullptr, nullptr, NTOK, D_IN_PROJ, D_MODEL);
        conv_silu_kernel<<<(NTOK * CONV_DIM + 255) / 256, 256>>>(
            z, cw + (size_t)i * CONV_DIM * DCONV, cb + (size_t)i * CONV_DIM, conv);
        dt_kernel<<<(NTOK * NHEADS) / 256, 256>>>(
            z, dtb + i * NHEADS, Alog + i * NHEADS, dt, dA);
        // MEASUREMENT: scan launched twice with identical args (second overwrites
        // with identical values). dur_us delta vs R13 = 4 x scan duration.
        scan_kernel<<<BATCH * NHEADS, 512>>>(conv, dt, dA, Dsk + i * NHEADS, y);
        scan_kernel<<<BATCH * NHEADS, 512>>>(conv, dt, dA, Dsk + i * NHEADS, y);
        gated_norm_kernel<<<NTOK, 256>>>(y, z, nw + (size_t)i * D_INNER, ynh, ynl);
        wsplit_t<<<dim3(D_MODEL/32, D_INNER/32), wsb>>>(
            Wout + (size_t)i * D_INNER * D_MODEL, wth, wtl, D_INNER, D_MODEL);
        gemm_bf3<0,0,1><<<dim3(D_MODEL/128, MT), 256, GEMM_SMEM_BYTES>>>(
            ynh, ynl, wth, wtl, nullptr, h, hh_, hl_, NTOK, D_MODEL, D_INNER);
    }

    // ---- output MLP ----
    wsplit_t<<<dim3(D_MODEL/32, D_MODEL/32), wsb>>>(ow1, wth, wtl, D_MODEL, D_MODEL);
    gemm_bf3<1,1,0><<<dim3(D_MODEL/128, MT), 256, GEMM_SMEM_BYTES>>>(
        hh_, hl_, wth, wtl, ob1, tmp, nullptr, nullptr, NTOK, D_MODEL, D_MODEL);
    dot_kernel<<<NTOK, 256>>>(tmp, ow2, ob2, out);
}

// round 15
// speedup vs baseline: 2.8339x; 2.8339x over previous
#include <cuda_runtime.h>
#include <cuda.h>
#include <cuda_bf16.h>
#include <math.h>
#include <stdint.h>

// ---------------- problem constants ----------------
#define BATCH     4
#define SEQ       512
#define NTOK      (BATCH*SEQ)          // 2048
#define STATE     510
#define D_MODEL   1024
#define D_INNER   2048
#define D_STATE   128
#define NHEADS    32
#define HEADDIM   64
#define DCONV     4
#define CONV_DIM  (D_INNER + 2*D_STATE)            // 2304
#define D_IN_PROJ (2*D_INNER + 2*D_STATE + NHEADS) // 4384
#define NBLOCKS   4

// ---------------- scratch (device globals, no allocs) ----------------
__device__ float g_tmp [NTOK * D_MODEL];
__device__ float g_h   [NTOK * D_MODEL];
__device__ float g_z   [NTOK * D_IN_PROJ];
__device__ float g_conv[NTOK * CONV_DIM];
__device__ float g_dt  [NTOK * NHEADS];
__device__ float g_dA  [NTOK * NHEADS];
__device__ float g_y   [NTOK * D_INNER];

// bf16 hi/lo operand buffers (16B aligned for cp.async)
__device__ __align__(16) __nv_bfloat16 g_cat_h[NTOK * 512];
__device__ __align__(16) __nv_bfloat16 g_cat_l[NTOK * 512];
__device__ __align__(16) __nv_bfloat16 g_tmp_h[NTOK * D_MODEL];
__device__ __align__(16) __nv_bfloat16 g_tmp_l[NTOK * D_MODEL];
__device__ __align__(16) __nv_bfloat16 g_h_h  [NTOK * D_MODEL];
__device__ __align__(16) __nv_bfloat16 g_h_l  [NTOK * D_MODEL];
__device__ __align__(16) __nv_bfloat16 g_yn_h [NTOK * D_INNER];
__device__ __align__(16) __nv_bfloat16 g_yn_l [NTOK * D_INNER];
// transposed weight scratch (max: Win^T = 4384 x 1024; in-MLP uses two regions)
__device__ __align__(16) __nv_bfloat16 g_wth[D_IN_PROJ * D_MODEL];
__device__ __align__(16) __nv_bfloat16 g_wtl[D_IN_PROJ * D_MODEL];

// ================= helpers =================
__device__ __forceinline__ uint32_t smem_to_u32(const void* p) {
    uint32_t a;
    asm("{ .reg .u64 t; cvta.to.shared.u64 t, %1; cvt.u32.u64 %0, t; }" : "=r"(a) : "l"(p));
    return a;
}
#define LDSM_X4(r0, r1, r2, r3, addr) \
    asm volatile("ldmatrix.sync.aligned.m8n8.x4.shared.b16 {%0,%1,%2,%3}, [%4];" \
        : "=r"(r0), "=r"(r1), "=r"(r2), "=r"(r3) : "r"(addr))
#define CP_ASYNC16(dst, src) \
    asm volatile("cp.async.ca.shared.global [%0], [%1], 16;" :: "r"(dst), "l"(src) : "memory")
#define CP_ASYNC4(dst, src) \
    asm volatile("cp.async.ca.shared.global [%0], [%1], 4;" :: "r"(dst), "l"(src) : "memory")
#define CP_COMMIT() asm volatile("cp.async.commit_group;" ::: "memory")
#define CP_WAIT1()  asm volatile("cp.async.wait_group 1;" ::: "memory")
#define CP_WAIT0()  asm volatile("cp.async.wait_group 0;" ::: "memory")

// Split x0,x1 into packed bf16x2 hi and lo parts (hi half of reg = x1).
__device__ __forceinline__ void bf16x2split(float x0, float x1, uint32_t& hi, uint32_t& lo) {
    uint32_t h;
    asm("cvt.rn.bf16x2.f32 %0, %1, %2;" : "=r"(h) : "f"(x1), "f"(x0));
    float h0 = __uint_as_float(h << 16);
    float h1 = __uint_as_float(h & 0xffff0000u);
    float l0 = x0 - h0;
    float l1 = x1 - h1;
    hi = h;
    asm("cvt.rn.bf16x2.f32 %0, %1, %2;" : "=r"(lo) : "f"(l1), "f"(l0));
}

#define MMA_BF16(cr, a, b) \
    asm volatile("mma.sync.aligned.m16n8k16.row.col.f32.bf16.bf16.f32 " \
        "{%0,%1,%2,%3},{%4,%5,%6,%7},{%8,%9},{%0,%1,%2,%3};" \
        : "+f"((cr)[0]), "+f"((cr)[1]), "+f"((cr)[2]), "+f"((cr)[3]) \
        : "r"((a)[0]), "r"((a)[1]), "r"((a)[2]), "r"((a)[3]), \
          "r"((b)[0]), "r"((b)[1]))

// ================= weight split+transpose: W[K,N] -> Th/Tl[N,K] bf16 =================
__global__ __launch_bounds__(256)
void wsplit_t(const float* __restrict__ W, __nv_bfloat16* __restrict__ Th,
              __nv_bfloat16* __restrict__ Tl, int K, int N)
{
    __shared__ float t[32][33];
    int n0 = blockIdx.x * 32, k0 = blockIdx.y * 32;
    int tx = threadIdx.x, ty = threadIdx.y;   // 32 x 8
    #pragma unroll
    for (int i = 0; i < 32; i += 8)
        t[ty + i][tx] = W[(size_t)(k0 + ty + i) * N + n0 + tx];
    __syncthreads();
    #pragma unroll
    for (int i = 0; i < 32; i += 8) {
        int n = n0 + ty + i, k = k0 + tx;
        float v = t[tx][ty + i];
        __nv_bfloat16 h = __float2bfloat16(v);
        Th[(size_t)n * K + k] = h;
        Tl[(size_t)n * K + k] = __float2bfloat16(v - __bfloat162float(h));
    }
}

// ================= bf16x3 GEMM, pre-split operands, ldmatrix fragments =================
#define STAGE_BYTES 40960
#define GEMM_SMEM_BYTES (2 * STAGE_BYTES)

template<int BIAS, int RELU, int WSPLIT>
__global__ __launch_bounds__(256, 2)
void gemm_bf3(const __nv_bfloat16* __restrict__ Ah, const __nv_bfloat16* __restrict__ Al,
              const __nv_bfloat16* __restrict__ Bh, const __nv_bfloat16* __restrict__ Bl,
              const float* __restrict__ bias, float* __restrict__ C,
              __nv_bfloat16* __restrict__ Ch, __nv_bfloat16* __restrict__ Cl,
              int M, int N, int K)
{
    extern __shared__ char smc[];
    const uint32_t sb = smem_to_u32(smc);

    const int tid = threadIdx.x, lane = tid & 31, w = tid >> 5;
    const int wm = w >> 2, wn = w & 3;          // warp grid 2(m) x 4(n)
    const int grp = lane >> 2, kq = lane & 3;
    const int m0 = blockIdx.y * 128, n0 = blockIdx.x * 128;

    const int r = tid >> 2, q = tid & 3;        // cp.async: row 0..63, 16B chunk 0..3

    const uint32_t laneA = (uint32_t)((lane & 15) * 80 + (lane >> 4) * 16);
    const uint32_t laneB = (uint32_t)((((lane >> 4) & 1) * 8 + (lane & 7)) * 80
                                      + ((lane >> 3) & 1) * 16);
    const uint32_t aWarp = (uint32_t)(wm * 64 * 80);
    const uint32_t bWarp = (uint32_t)(wn * 32 * 80);

    float c[4][4][4];
    #pragma unroll
    for (int i = 0; i < 4; i++)
        #pragma unroll
        for (int j = 0; j < 4; j++)
            #pragma unroll
            for (int p = 0; p < 4; p++) c[i][j][p] = 0.f;

    const int nch = K >> 5;

    int br0 = n0 + r;       if (br0 >= N) br0 = N - 1;
    int br1 = n0 + r + 64;  if (br1 >= N) br1 = N - 1;

    auto issue = [&](int ch) {
        const uint32_t st = sb + (uint32_t)(ch & 1) * STAGE_BYTES;
        const int k0 = ch << 5;
        const size_t aoff = (size_t)(m0 + r) * K + k0 + q * 8;
        CP_ASYNC16(st + (uint32_t)(r * 80 + q * 16),                 Ah + aoff);
        CP_ASYNC16(st + (uint32_t)((r + 64) * 80 + q * 16),          Ah + aoff + (size_t)64 * K);
        CP_ASYNC16(st + 10240u + (uint32_t)(r * 80 + q * 16),        Al + aoff);
        CP_ASYNC16(st + 10240u + (uint32_t)((r + 64) * 80 + q * 16), Al + aoff + (size_t)64 * K);
        const size_t b0off = (size_t)br0 * K + k0 + q * 8;
        const size_t b1off = (size_t)br1 * K + k0 + q * 8;
        CP_ASYNC16(st + 20480u + (uint32_t)(r * 80 + q * 16),        Bh + b0off);
        CP_ASYNC16(st + 20480u + (uint32_t)((r + 64) * 80 + q * 16), Bh + b1off);
        CP_ASYNC16(st + 30720u + (uint32_t)(r * 80 + q * 16),        Bl + b0off);
        CP_ASYNC16(st + 30720u + (uint32_t)((r + 64) * 80 + q * 16), Bl + b1off);
        CP_COMMIT();
    };

    issue(0);

    for (int ch = 0; ch < nch; ch++) {
        if (ch + 1 < nch) { issue(ch + 1); CP_WAIT1(); }
        else              { CP_WAIT0(); }
        __syncthreads();

        const uint32_t st = sb + (uint32_t)(ch & 1) * STAGE_BYTES;

        #pragma unroll
        for (int ks = 0; ks < 2; ks++) {
            const uint32_t ko = (uint32_t)(ks * 32);
            uint32_t bh[4][2], bl[4][2];
            #pragma unroll
            for (int pa = 0; pa < 2; pa++) {
                uint32_t ba = st + 20480u + bWarp + (uint32_t)(pa * 16 * 80) + laneB + ko;
                LDSM_X4(bh[2*pa][0], bh[2*pa][1], bh[2*pa+1][0], bh[2*pa+1][1], ba);
                uint32_t bla = ba + 10240u;
                LDSM_X4(bl[2*pa][0], bl[2*pa][1], bl[2*pa+1][0], bl[2*pa+1][1], bla);
            }
            #pragma unroll
            for (int ma = 0; ma < 4; ma++) {
                uint32_t aa = st + aWarp + (uint32_t)(ma * 16 * 80) + laneA + ko;
                uint32_t ah[4], al[4];
                LDSM_X4(ah[0], ah[1], ah[2], ah[3], aa);
                LDSM_X4(al[0], al[1], al[2], al[3], aa + 10240u);
                #pragma unroll
                for (int na = 0; na < 4; na++) {
                    MMA_BF16(c[ma][na], ah, bh[na]);
                    MMA_BF16(c[ma][na], ah, bl[na]);
                    MMA_BF16(c[ma][na], al, bh[na]);
                }
            }
        }
        __syncthreads();
    }

    // ---- epilogue ----
    #pragma unroll
    for (int ma = 0; ma < 4; ma++) {
        int row = m0 + wm * 64 + ma * 16 + grp;
        #pragma unroll
        for (int na = 0; na < 4; na++) {
            int col = n0 + wn * 32 + na * 8 + kq * 2;
            if (col < N) {
                float b0 = 0.f, b1 = 0.f;
                if (BIAS) { b0 = bias[col]; b1 = bias[col + 1]; }
                float v0 = c[ma][na][0] + b0, v1 = c[ma][na][1] + b1;
                float v2 = c[ma][na][2] + b0, v3 = c[ma][na][3] + b1;
                if (RELU) {
                    v0 = fmaxf(v0, 0.f); v1 = fmaxf(v1, 0.f);
                    v2 = fmaxf(v2, 0.f); v3 = fmaxf(v3, 0.f);
                }
                *(float2*)(C + (size_t)row * N + col)       = make_float2(v0, v1);
                *(float2*)(C + (size_t)(row + 8) * N + col) = make_float2(v2, v3);
                if (WSPLIT) {
                    uint32_t h01, l01, h23, l23;
                    bf16x2split(v0, v1, h01, l01);
                    bf16x2split(v2, v3, h23, l23);
                    *(uint32_t*)(Ch + (size_t)row * N + col)       = h01;
                    *(uint32_t*)(Cl + (size_t)row * N + col)       = l01;
                    *(uint32_t*)(Ch + (size_t)(row + 8) * N + col) = h23;
                    *(uint32_t*)(Cl + (size_t)(row + 8) * N + col) = l23;
                }
            }
        }
    }
}

// ---------------- helpers ----------------
__device__ __forceinline__ float siluf(float v) { return v / (1.f + expf(-v)); }

__device__ __forceinline__ float blockReduceSum256(float v) {
    __shared__ float s[8];
    __shared__ float tot;
    int lane = threadIdx.x & 31, w = threadIdx.x >> 5;
    #pragma unroll
    for (int o = 16; o; o >>= 1) v += __shfl_xor_sync(0xffffffffu, v, o);
    if (lane == 0) s[w] = v;
    __syncthreads();
    if (threadIdx.x < 32) {
        float t = (threadIdx.x < 8) ? s[threadIdx.x] : 0.f;
        #pragma unroll
        for (int o = 4; o; o >>= 1) t += __shfl_xor_sync(0xffffffffu, t, o);
        if (threadIdx.x == 0) tot = t;
    }
    __syncthreads();
    return tot;
}

// ---------------- elementwise kernels ----------------
__global__ void concat_kernel(const float* __restrict__ x, const float* __restrict__ sl,
                              const float* __restrict__ cr,
                              __nv_bfloat16* __restrict__ oh, __nv_bfloat16* __restrict__ ol)
{
    int idx = blockIdx.x * blockDim.x + threadIdx.x;   // NTOK*512
    int c = idx & 511, r = idx >> 9;
    float v;
    if (c < STATE)      v = x[(size_t)r * STATE + c];
    else if (c == STATE) v = sl[r];
    else                 v = cr[r];
    __nv_bfloat16 h = __float2bfloat16(v);
    oh[idx] = h;
    ol[idx] = __float2bfloat16(v - __bfloat162float(h));
}

__global__ void conv_silu_kernel(const float* __restrict__ zb, const float* __restrict__ cw,
                                 const float* __restrict__ cb, float* __restrict__ out)
{
    int idx = blockIdx.x * blockDim.x + threadIdx.x;   // NTOK*CONV_DIM
    if (idx >= NTOK * CONV_DIM) return;
    int ch = idx % CONV_DIM;
    int t  = idx / CONV_DIM;
    int l = t & (SEQ - 1), b = t >> 9;
    float s = cb[ch];
    #pragma unroll
    for (int k = 0; k < DCONV; k++) {
        int ll = l - (DCONV - 1) + k;
        if (ll >= 0)
            s = fmaf(zb[((size_t)(b * SEQ + ll)) * D_IN_PROJ + D_INNER + ch], cw[ch * DCONV + k], s);
    }
    out[idx] = siluf(s);
}

__global__ void dt_kernel(const float* __restrict__ zb, const float* __restrict__ dtb,
                          const float* __restrict__ Alog,
                          float* __restrict__ dt, float* __restrict__ dA)
{
    int idx = blockIdx.x * blockDim.x + threadIdx.x;   // NTOK*NHEADS
    if (idx >= NTOK * NHEADS) return;
    int hh = idx & (NHEADS - 1), row = idx >> 5;
    float v = zb[(size_t)row * D_IN_PROJ + (D_INNER + CONV_DIM) + hh] + dtb[hh];
    float sp = (v > 20.f) ? v : log1pf(expf(v));
    float a = -expf(Alog[hh]);
    dt[idx] = sp;
    dA[idx] = expf(sp * a);
}

// ---------------- selective scan: 1 CTA per (b, head), 512 threads ----------------
// Conflict-free smem layout: B/C rows stored chunk-permuted. Original 16B chunk
// c = nq*4+i is stored at position c' = i*8+nq, so a warp load at fixed i hits
// chunks {i*8+nq}, all distinct mod 8 -> no bank conflicts (was 4-way).
#define SCHUNK 16
#define NCHUNK (SEQ / SCHUNK)

__global__ __launch_bounds__(512)
void scan_kernel(const float* __restrict__ conv, const float* __restrict__ dt,
                 const float* __restrict__ dA, const float* __restrict__ Dsk,
                 float* __restrict__ y)
{
    __shared__ float sB[2][SCHUNK][D_STATE];
    __shared__ float sC[2][SCHUNK][D_STATE];
    __shared__ float sX[2][SCHUNK][HEADDIM];
    __shared__ float sdt[2][SCHUNK];
    __shared__ float sda[2][SCHUNK];

    int bh = blockIdx.x;
    int b = bh >> 5, hh = bh & 31;
    int tid = threadIdx.x;
    int p = tid >> 3, nq = tid & 7;

    const size_t convb = (size_t)b * SEQ * CONV_DIM;
    const uint32_t sBa = smem_to_u32(&sB[0][0][0]);
    const uint32_t sCa = smem_to_u32(&sC[0][0][0]);
    const uint32_t sXa = smem_to_u32(&sX[0][0][0]);
    const uint32_t sdta = smem_to_u32(&sdt[0][0]);
    const uint32_t sdaa = smem_to_u32(&sda[0][0]);

    auto issue = [&](int ch) {
        const int l0 = ch * SCHUNK;
        const int buf = ch & 1;
        {   // B: chunk-permuted dst
            int st = tid >> 5, f4 = tid & 31;
            int dstc = (f4 & 3) * 8 + (f4 >> 2);
            const float* src = conv + convb + (size_t)(l0 + st) * CONV_DIM + D_INNER + f4 * 4;
            CP_ASYNC16(sBa + (uint32_t)(buf * SCHUNK * D_STATE + st * D_STATE + dstc * 4) * 4u, src);
        }
        {   // C: chunk-permuted dst
            int st = tid >> 5, f4 = tid & 31;
            int dstc = (f4 & 3) * 8 + (f4 >> 2);
            const float* src = conv + convb + (size_t)(l0 + st) * CONV_DIM + D_INNER + D_STATE + f4 * 4;
            CP_ASYNC16(sCa + (uint32_t)(buf * SCHUNK * D_STATE + st * D_STATE + dstc * 4) * 4u, src);
        }
        if (tid < 256) {
            int st = tid >> 4, f4 = tid & 15;
            const float* src = conv + convb + (size_t)(l0 + st) * CONV_DIM + hh * HEADDIM + f4 * 4;
            CP_ASYNC16(sXa + (uint32_t)(buf * SCHUNK * HEADDIM + st * HEADDIM + f4 * 4) * 4u, src);
        } else if (tid < 272) {
            int s = tid - 256;
            CP_ASYNC4(sdta + (uint32_t)(buf * SCHUNK + s) * 4u,
                      dt + (size_t)(b * SEQ + l0 + s) * NHEADS + hh);
        } else if (tid < 288) {
            int s = tid - 272;
            CP_ASYNC4(sdaa + (uint32_t)(buf * SCHUNK + s) * 4u,
                      dA + (size_t)(b * SEQ + l0 + s) * NHEADS + hh);
        }
        CP_COMMIT();
    };

    float hs[16];
    #pragma unroll
    for (int i = 0; i < 16; i++) hs[i] = 0.f;
    float dsk = Dsk[hh];

    issue(0);

    for (int ch = 0; ch < NCHUNK; ch++) {
        if (ch + 1 < NCHUNK) { issue(ch + 1); CP_WAIT1(); }
        else                 { CP_WAIT0(); }
        __syncthreads();
        const int buf = ch & 1;

        #pragma unroll 2
        for (int s = 0; s < SCHUNK; s++) {
            int l = ch * SCHUNK + s;
            float dtv = sdt[buf][s];
            float dav = sda[buf][s];
            float xp = sX[buf][s][p];
            float coef = dtv * xp;
            const float4* B4 = (const float4*)&sB[buf][s][0];
            const float4* C4 = (const float4*)&sC[buf][s][0];
            // permuted chunk layout: chunk for (i, nq) lives at i*8+nq
            float4 bv0 = B4[nq], bv1 = B4[8 + nq], bv2 = B4[16 + nq], bv3 = B4[24 + nq];
            float4 cv0 = C4[nq], cv1 = C4[8 + nq], cv2 = C4[16 + nq], cv3 = C4[24 + nq];
            hs[0]  = fmaf(hs[0],  dav, coef * bv0.x);
            hs[1]  = fmaf(hs[1],  dav, coef * bv0.y);
            hs[2]  = fmaf(hs[2],  dav, coef * bv0.z);
            hs[3]  = fmaf(hs[3],  dav, coef * bv0.w);
            hs[4]  = fmaf(hs[4],  dav, coef * bv1.x);
            hs[5]  = fmaf(hs[5],  dav, coef * bv1.y);
            hs[6]  = fmaf(hs[6],  dav, coef * bv1.z);
            hs[7]  = fmaf(hs[7],  dav, coef * bv1.w);
            hs[8]  = fmaf(hs[8],  dav, coef * bv2.x);
            hs[9]  = fmaf(hs[9],  dav, coef * bv2.y);
            hs[10] = fmaf(hs[10], dav, coef * bv2.z);
            hs[11] = fmaf(hs[11], dav, coef * bv2.w);
            hs[12] = fmaf(hs[12], dav, coef * bv3.x);
            hs[13] = fmaf(hs[13], dav, coef * bv3.y);
            hs[14] = fmaf(hs[14], dav, coef * bv3.z);
            hs[15] = fmaf(hs[15], dav, coef * bv3.w);
            float a0 = hs[0] * cv0.x;
            float a1 = hs[1] * cv0.y;
            float a2 = hs[2] * cv0.z;
            float a3 = hs[3] * cv0.w;
            a0 = fmaf(hs[4],  cv1.x, a0);
            a1 = fmaf(hs[5],  cv1.y, a1);
            a2 = fmaf(hs[6],  cv1.z, a2);
            a3 = fmaf(hs[7],  cv1.w, a3);
            a0 = fmaf(hs[8],  cv2.x, a0);
            a1 = fmaf(hs[9],  cv2.y, a1);
            a2 = fmaf(hs[10], cv2.z, a2);
            a3 = fmaf(hs[11], cv2.w, a3);
            a0 = fmaf(hs[12], cv3.x, a0);
            a1 = fmaf(hs[13], cv3.y, a1);
            a2 = fmaf(hs[14], cv3.z, a2);
            a3 = fmaf(hs[15], cv3.w, a3);
            float acc = (a0 + a1) + (a2 + a3);
            acc += __shfl_xor_sync(0xffffffffu, acc, 1);
            acc += __shfl_xor_sync(0xffffffffu, acc, 2);
            acc += __shfl_xor_sync(0xffffffffu, acc, 4);
            if (nq == 0)
                y[((size_t)(b * SEQ + l)) * D_INNER + hh * HEADDIM + p] = acc + dsk * xp;
        }
        __syncthreads();
    }
}

// ---------------- gated RMSNorm (writes bf16 hi/lo for next GEMM) ----------------
__global__ __launch_bounds__(256)
void gated_norm_kernel(const float* __restrict__ y, const float* __restrict__ z,
                       const float* __restrict__ nw,
                       __nv_bfloat16* __restrict__ oh, __nv_bfloat16* __restrict__ ol)
{
    int r = blockIdx.x;
    float g[8];
    float ss = 0.f;
    #pragma unroll
    for (int j = 0; j < 8; j++) {
        int c = j * 256 + threadIdx.x;
        float zv = z[(size_t)r * D_IN_PROJ + c];
        float gv = y[(size_t)r * D_INNER + c] * siluf(zv);
        g[j] = gv;
        ss = fmaf(gv, gv, ss);
    }
    ss = blockReduceSum256(ss);
    float inv = rsqrtf(ss / (float)D_INNER + 1e-5f);
    #pragma unroll
    for (int j = 0; j < 8; j++) {
        int c = j * 256 + threadIdx.x;
        float v = g[j] * inv * nw[c];
        __nv_bfloat16 h = __float2bfloat16(v);
        oh[(size_t)r * D_INNER + c] = h;
        ol[(size_t)r * D_INNER + c] = __float2bfloat16(v - __bfloat162float(h));
    }
}

// ---------------- final N=1 projection ----------------
__global__ __launch_bounds__(256)
void dot_kernel(const float* __restrict__ t, const float* __restrict__ w,
                const float* __restrict__ b, float* __restrict__ out)
{
    int r = blockIdx.x;
    float s = 0.f;
    for (int k = threadIdx.x; k < D_MODEL; k += 256)
        s = fmaf(t[(size_t)r * D_MODEL + k], w[k], s);
    s = blockReduceSum256(s);
    if (threadIdx.x == 0) out[r] = s + b[0];
}

// ---------------- launch ----------------
extern "C" void kernel_launch(void* const* d_in, const int* in_sizes, int n_in,
                              void* d_out, int out_size)
{
    const float* x    = (const float*)d_in[0];
    const float* sl   = (const float*)d_in[1];
    const float* cr   = (const float*)d_in[2];
    const float* iw1  = (const float*)d_in[3];
    const float* ib1  = (const float*)d_in[4];
    const float* iw2  = (const float*)d_in[5];
    const float* ib2  = (const float*)d_in[6];
    const float* Win  = (const float*)d_in[7];
    const float* cw   = (const float*)d_in[8];
    const float* cb   = (const float*)d_in[9];
    const float* dtb  = (const float*)d_in[10];
    const float* Alog = (const float*)d_in[11];
    const float* Dsk  = (const float*)d_in[12];
    const float* nw   = (const float*)d_in[13];
    const float* Wout = (const float*)d_in[14];
    const float* ow1  = (const float*)d_in[15];
    const float* ob1  = (const float*)d_in[16];
    const float* ow2  = (const float*)d_in[17];
    const float* ob2  = (const float*)d_in[18];
    float* out = (float*)d_out;

    float *tmp, *h, *z, *conv, *dt, *dA, *y;
    __nv_bfloat16 *cath, *catl, *tmph, *tmpl, *hh_, *hl_, *ynh, *ynl, *wth, *wtl;
    cudaGetSymbolAddress((void**)&tmp,  g_tmp);
    cudaGetSymbolAddress((void**)&h,    g_h);
    cudaGetSymbolAddress((void**)&z,    g_z);
    cudaGetSymbolAddress((void**)&conv, g_conv);
    cudaGetSymbolAddress((void**)&dt,   g_dt);
    cudaGetSymbolAddress((void**)&dA,   g_dA);
    cudaGetSymbolAddress((void**)&y,    g_y);
    cudaGetSymbolAddress((void**)&cath, g_cat_h);
    cudaGetSymbolAddress((void**)&catl, g_cat_l);
    cudaGetSymbolAddress((void**)&tmph, g_tmp_h);
    cudaGetSymbolAddress((void**)&tmpl, g_tmp_l);
    cudaGetSymbolAddress((void**)&hh_,  g_h_h);
    cudaGetSymbolAddress((void**)&hl_,  g_h_l);
    cudaGetSymbolAddress((void**)&ynh,  g_yn_h);
    cudaGetSymbolAddress((void**)&ynl,  g_yn_l);
    cudaGetSymbolAddress((void**)&wth,  g_wth);
    cudaGetSymbolAddress((void**)&wtl,  g_wtl);

    cudaFuncSetAttribute(gemm_bf3<1,1,1>, cudaFuncAttributeMaxDynamicSharedMemorySize, GEMM_SMEM_BYTES);
    cudaFuncSetAttribute(gemm_bf3<1,0,1>, cudaFuncAttributeMaxDynamicSharedMemorySize, GEMM_SMEM_BYTES);
    cudaFuncSetAttribute(gemm_bf3<0,0,0>, cudaFuncAttributeMaxDynamicSharedMemorySize, GEMM_SMEM_BYTES);
    cudaFuncSetAttribute(gemm_bf3<0,0,1>, cudaFuncAttributeMaxDynamicSharedMemorySize, GEMM_SMEM_BYTES);
    cudaFuncSetAttribute(gemm_bf3<1,1,0>, cudaFuncAttributeMaxDynamicSharedMemorySize, GEMM_SMEM_BYTES);

    const int MT = NTOK / 128;   // 16 M-tiles
    dim3 wsb(32, 8);

    // ---- input MLP (wsplits hoisted so launch index 3 = gemm_bf3 for ncu) ----
    wsplit_t<<<dim3(512/32, 512/32), wsb>>>(iw1, wth, wtl, 512, 512);                 // 0
    __nv_bfloat16* wth2 = wth + (size_t)512 * 512;
    __nv_bfloat16* wtl2 = wtl + (size_t)512 * 512;
    wsplit_t<<<dim3(D_MODEL/32, 512/32), wsb>>>(iw2, wth2, wtl2, 512, D_MODEL);       // 1
    concat_kernel<<<NTOK * 512 / 256, 256>>>(x, sl, cr, cath, catl);                  // 2
    gemm_bf3<1,1,1><<<dim3(512/128, MT), 256, GEMM_SMEM_BYTES>>>(                     // 3 <- profiled
        cath, catl, wth, wtl, ib1, tmp, tmph, tmpl, NTOK, 512, 512);
    gemm_bf3<1,0,1><<<dim3(D_MODEL/128, MT), 256, GEMM_SMEM_BYTES>>>(
        tmph, tmpl, wth2, wtl2, ib2, h, hh_, hl_, NTOK, D_MODEL, 512);

    for (int i = 0; i < NBLOCKS; i++) {
        wsplit_t<<<dim3(D_IN_PROJ/32, D_MODEL/32), wsb>>>(
            Win + (size_t)i * D_MODEL * D_IN_PROJ, wth, wtl, D_MODEL, D_IN_PROJ);
        gemm_bf3<0,0,0><<<dim3((D_IN_PROJ + 127)/128, MT), 256, GEMM_SMEM_BYTES>>>(
            hh_, hl_, wth, wtl, nullptr, z, nullptr, nullptr, NTOK, D_IN_PROJ, D_MODEL);
        conv_silu_kernel<<<(NTOK * CONV_DIM + 255) / 256, 256>>>(
            z, cw + (size_t)i * CONV_DIM * DCONV, cb + (size_t)i * CONV_DIM, conv);
        dt_kernel<<<(NTOK * NHEADS) / 256, 256>>>(
            z, dtb + i * NHEADS, Alog + i * NHEADS, dt, dA);
        scan_kernel<<<BATCH * NHEADS, 512>>>(conv, dt, dA, Dsk + i * NHEADS, y);
        gated_norm_kernel<<<NTOK, 256>>>(y, z, nw + (size_t)i * D_INNER, ynh, ynl);
        wsplit_t<<<dim3(D_MODEL/32, D_INNER/32), wsb>>>(
            Wout + (size_t)i * D_INNER * D_MODEL, wth, wtl, D_INNER, D_MODEL);
        gemm_bf3<0,0,1><<<dim3(D_MODEL/128, MT), 256, GEMM_SMEM_BYTES>>>(
            ynh, ynl, wth, wtl, nullptr, h, hh_, hl_, NTOK, D_MODEL, D_INNER);
    }

    // ---- output MLP ----
    wsplit_t<<<dim3(D_MODEL/32, D_MODEL/32), wsb>>>(ow1, wth, wtl, D_MODEL, D_MODEL);
    gemm_bf3<1,1,0><<<dim3(D_MODEL/128, MT), 256, GEMM_SMEM_BYTES>>>(
        hh_, hl_, wth, wtl, ob1, tmp, nullptr, nullptr, NTOK, D_MODEL, D_MODEL);
    dot_kernel<<<NTOK, 256>>>(tmp, ow2, ob2, out);
}

// round 17
// speedup vs baseline: 3.2915x; 1.1614x over previous
#include <cuda_runtime.h>
#include <cuda.h>
#include <cuda_bf16.h>
#include <math.h>
#include <stdint.h>

// ---------------- problem constants ----------------
#define BATCH     4
#define SEQ       512
#define NTOK      (BATCH*SEQ)          // 2048
#define STATE     510
#define D_MODEL   1024
#define D_INNER   2048
#define D_STATE   128
#define NHEADS    32
#define HEADDIM   64
#define DCONV     4
#define CONV_DIM  (D_INNER + 2*D_STATE)            // 2304
#define D_IN_PROJ (2*D_INNER + 2*D_STATE + NHEADS) // 4384
#define NBLOCKS   4

typedef unsigned long long ull;

// ---------------- scratch (device globals, no allocs) ----------------
__device__ float g_tmp [NTOK * D_MODEL];
__device__ float g_h   [NTOK * D_MODEL];
__device__ float g_z   [NTOK * D_IN_PROJ];
__device__ float g_conv[NTOK * CONV_DIM];
__device__ float g_dt  [NTOK * NHEADS];
__device__ float g_dA  [NTOK * NHEADS];
__device__ float g_y   [NTOK * D_INNER];

// bf16 hi/lo operand buffers (16B aligned for cp.async)
__device__ __align__(16) __nv_bfloat16 g_cat_h[NTOK * 512];
__device__ __align__(16) __nv_bfloat16 g_cat_l[NTOK * 512];
__device__ __align__(16) __nv_bfloat16 g_tmp_h[NTOK * D_MODEL];
__device__ __align__(16) __nv_bfloat16 g_tmp_l[NTOK * D_MODEL];
__device__ __align__(16) __nv_bfloat16 g_h_h  [NTOK * D_MODEL];
__device__ __align__(16) __nv_bfloat16 g_h_l  [NTOK * D_MODEL];
__device__ __align__(16) __nv_bfloat16 g_yn_h [NTOK * D_INNER];
__device__ __align__(16) __nv_bfloat16 g_yn_l [NTOK * D_INNER];
// transposed weight scratch (max: Win^T = 4384 x 1024; in-MLP uses two regions)
__device__ __align__(16) __nv_bfloat16 g_wth[D_IN_PROJ * D_MODEL];
__device__ __align__(16) __nv_bfloat16 g_wtl[D_IN_PROJ * D_MODEL];

// ================= helpers =================
__device__ __forceinline__ uint32_t smem_to_u32(const void* p) {
    uint32_t a;
    asm("{ .reg .u64 t; cvta.to.shared.u64 t, %1; cvt.u32.u64 %0, t; }" : "=r"(a) : "l"(p));
    return a;
}
#define LDSM_X4(r0, r1, r2, r3, addr) \
    asm volatile("ldmatrix.sync.aligned.m8n8.x4.shared.b16 {%0,%1,%2,%3}, [%4];" \
        : "=r"(r0), "=r"(r1), "=r"(r2), "=r"(r3) : "r"(addr))
#define CP_ASYNC16(dst, src) \
    asm volatile("cp.async.ca.shared.global [%0], [%1], 16;" :: "r"(dst), "l"(src) : "memory")
#define CP_ASYNC4(dst, src) \
    asm volatile("cp.async.ca.shared.global [%0], [%1], 4;" :: "r"(dst), "l"(src) : "memory")
#define CP_COMMIT() asm volatile("cp.async.commit_group;" ::: "memory")
#define CP_WAIT1()  asm volatile("cp.async.wait_group 1;" ::: "memory")
#define CP_WAIT0()  asm volatile("cp.async.wait_group 0;" ::: "memory")

// Blackwell packed fp32x2 ops (base sm_100 PTX, no 'a' suffix needed)
#define MUL2(d, a, b) \
    asm("mul.rn.f32x2 %0, %1, %2;" : "=l"(d) : "l"(a), "l"(b))
#define FMA2(d, a, b, c) \
    asm("fma.rn.f32x2 %0, %1, %2, %3;" : "=l"(d) : "l"(a), "l"(b), "l"(c))
__device__ __forceinline__ ull pk2(float lo, float hi) {
    ull d;
    asm("mov.b64 %0, {%1, %2};" : "=l"(d) : "f"(lo), "f"(hi));
    return d;
}
__device__ __forceinline__ void upk2(ull v, float& lo, float& hi) {
    asm("mov.b64 {%0, %1}, %2;" : "=f"(lo), "=f"(hi) : "l"(v));
}

// Split x0,x1 into packed bf16x2 hi and lo parts (hi half of reg = x1).
__device__ __forceinline__ void bf16x2split(float x0, float x1, uint32_t& hi, uint32_t& lo) {
    uint32_t h;
    asm("cvt.rn.bf16x2.f32 %0, %1, %2;" : "=r"(h) : "f"(x1), "f"(x0));
    float h0 = __uint_as_float(h << 16);
    float h1 = __uint_as_float(h & 0xffff0000u);
    float l0 = x0 - h0;
    float l1 = x1 - h1;
    hi = h;
    asm("cvt.rn.bf16x2.f32 %0, %1, %2;" : "=r"(lo) : "f"(l1), "f"(l0));
}

#define MMA_BF16(cr, a, b) \
    asm volatile("mma.sync.aligned.m16n8k16.row.col.f32.bf16.bf16.f32 " \
        "{%0,%1,%2,%3},{%4,%5,%6,%7},{%8,%9},{%0,%1,%2,%3};" \
        : "+f"((cr)[0]), "+f"((cr)[1]), "+f"((cr)[2]), "+f"((cr)[3]) \
        : "r"((a)[0]), "r"((a)[1]), "r"((a)[2]), "r"((a)[3]), \
          "r"((b)[0]), "r"((b)[1]))

// ================= weight split+transpose: W[K,N] -> Th/Tl[N,K] bf16 =================
__global__ __launch_bounds__(256)
void wsplit_t(const float* __restrict__ W, __nv_bfloat16* __restrict__ Th,
              __nv_bfloat16* __restrict__ Tl, int K, int N)
{
    __shared__ float t[32][33];
    int n0 = blockIdx.x * 32, k0 = blockIdx.y * 32;
    int tx = threadIdx.x, ty = threadIdx.y;   // 32 x 8
    #pragma unroll
    for (int i = 0; i < 32; i += 8)
        t[ty + i][tx] = W[(size_t)(k0 + ty + i) * N + n0 + tx];
    __syncthreads();
    #pragma unroll
    for (int i = 0; i < 32; i += 8) {
        int n = n0 + ty + i, k = k0 + tx;
        float v = t[tx][ty + i];
        __nv_bfloat16 h = __float2bfloat16(v);
        Th[(size_t)n * K + k] = h;
        Tl[(size_t)n * K + k] = __float2bfloat16(v - __bfloat162float(h));
    }
}

// ================= bf16x3 GEMM, pre-split operands, ldmatrix fragments =================
#define STAGE_BYTES 40960
#define GEMM_SMEM_BYTES (2 * STAGE_BYTES)

template<int BIAS, int RELU, int WSPLIT>
__global__ __launch_bounds__(256, 2)
void gemm_bf3(const __nv_bfloat16* __restrict__ Ah, const __nv_bfloat16* __restrict__ Al,
              const __nv_bfloat16* __restrict__ Bh, const __nv_bfloat16* __restrict__ Bl,
              const float* __restrict__ bias, float* __restrict__ C,
              __nv_bfloat16* __restrict__ Ch, __nv_bfloat16* __restrict__ Cl,
              int M, int N, int K)
{
    extern __shared__ char smc[];
    const uint32_t sb = smem_to_u32(smc);

    const int tid = threadIdx.x, lane = tid & 31, w = tid >> 5;
    const int wm = w >> 2, wn = w & 3;          // warp grid 2(m) x 4(n)
    const int grp = lane >> 2, kq = lane & 3;
    const int m0 = blockIdx.y * 128, n0 = blockIdx.x * 128;

    const int r = tid >> 2, q = tid & 3;        // cp.async: row 0..63, 16B chunk 0..3

    const uint32_t laneA = (uint32_t)((lane & 15) * 80 + (lane >> 4) * 16);
    const uint32_t laneB = (uint32_t)((((lane >> 4) & 1) * 8 + (lane & 7)) * 80
                                      + ((lane >> 3) & 1) * 16);
    const uint32_t aWarp = (uint32_t)(wm * 64 * 80);
    const uint32_t bWarp = (uint32_t)(wn * 32 * 80);

    float c[4][4][4];
    #pragma unroll
    for (int i = 0; i < 4; i++)
        #pragma unroll
        for (int j = 0; j < 4; j++)
            #pragma unroll
            for (int p = 0; p < 4; p++) c[i][j][p] = 0.f;

    const int nch = K >> 5;

    int br0 = n0 + r;       if (br0 >= N) br0 = N - 1;
    int br1 = n0 + r + 64;  if (br1 >= N) br1 = N - 1;

    auto issue = [&](int ch) {
        const uint32_t st = sb + (uint32_t)(ch & 1) * STAGE_BYTES;
        const int k0 = ch << 5;
        const size_t aoff = (size_t)(m0 + r) * K + k0 + q * 8;
        CP_ASYNC16(st + (uint32_t)(r * 80 + q * 16),                 Ah + aoff);
        CP_ASYNC16(st + (uint32_t)((r + 64) * 80 + q * 16),          Ah + aoff + (size_t)64 * K);
        CP_ASYNC16(st + 10240u + (uint32_t)(r * 80 + q * 16),        Al + aoff);
        CP_ASYNC16(st + 10240u + (uint32_t)((r + 64) * 80 + q * 16), Al + aoff + (size_t)64 * K);
        const size_t b0off = (size_t)br0 * K + k0 + q * 8;
        const size_t b1off = (size_t)br1 * K + k0 + q * 8;
        CP_ASYNC16(st + 20480u + (uint32_t)(r * 80 + q * 16),        Bh + b0off);
        CP_ASYNC16(st + 20480u + (uint32_t)((r + 64) * 80 + q * 16), Bh + b1off);
        CP_ASYNC16(st + 30720u + (uint32_t)(r * 80 + q * 16),        Bl + b0off);
        CP_ASYNC16(st + 30720u + (uint32_t)((r + 64) * 80 + q * 16), Bl + b1off);
        CP_COMMIT();
    };

    issue(0);

    for (int ch = 0; ch < nch; ch++) {
        if (ch + 1 < nch) { issue(ch + 1); CP_WAIT1(); }
        else              { CP_WAIT0(); }
        __syncthreads();

        const uint32_t st = sb + (uint32_t)(ch & 1) * STAGE_BYTES;

        #pragma unroll
        for (int ks = 0; ks < 2; ks++) {
            const uint32_t ko = (uint32_t)(ks * 32);
            uint32_t bh[4][2], bl[4][2];
            #pragma unroll
            for (int pa = 0; pa < 2; pa++) {
                uint32_t ba = st + 20480u + bWarp + (uint32_t)(pa * 16 * 80) + laneB + ko;
                LDSM_X4(bh[2*pa][0], bh[2*pa][1], bh[2*pa+1][0], bh[2*pa+1][1], ba);
                uint32_t bla = ba + 10240u;
                LDSM_X4(bl[2*pa][0], bl[2*pa][1], bl[2*pa+1][0], bl[2*pa+1][1], bla);
            }
            #pragma unroll
            for (int ma = 0; ma < 4; ma++) {
                uint32_t aa = st + aWarp + (uint32_t)(ma * 16 * 80) + laneA + ko;
                uint32_t ah[4], al[4];
                LDSM_X4(ah[0], ah[1], ah[2], ah[3], aa);
                LDSM_X4(al[0], al[1], al[2], al[3], aa + 10240u);
                #pragma unroll
                for (int na = 0; na < 4; na++) {
                    MMA_BF16(c[ma][na], ah, bh[na]);
                    MMA_BF16(c[ma][na], ah, bl[na]);
                    MMA_BF16(c[ma][na], al, bh[na]);
                }
            }
        }
        __syncthreads();
    }

    // ---- epilogue ----
    #pragma unroll
    for (int ma = 0; ma < 4; ma++) {
        int row = m0 + wm * 64 + ma * 16 + grp;
        #pragma unroll
        for (int na = 0; na < 4; na++) {
            int col = n0 + wn * 32 + na * 8 + kq * 2;
            if (col < N) {
                float b0 = 0.f, b1 = 0.f;
                if (BIAS) { b0 = bias[col]; b1 = bias[col + 1]; }
                float v0 = c[ma][na][0] + b0, v1 = c[ma][na][1] + b1;
                float v2 = c[ma][na][2] + b0, v3 = c[ma][na][3] + b1;
                if (RELU) {
                    v0 = fmaxf(v0, 0.f); v1 = fmaxf(v1, 0.f);
                    v2 = fmaxf(v2, 0.f); v3 = fmaxf(v3, 0.f);
                }
                *(float2*)(C + (size_t)row * N + col)       = make_float2(v0, v1);
                *(float2*)(C + (size_t)(row + 8) * N + col) = make_float2(v2, v3);
                if (WSPLIT) {
                    uint32_t h01, l01, h23, l23;
                    bf16x2split(v0, v1, h01, l01);
                    bf16x2split(v2, v3, h23, l23);
                    *(uint32_t*)(Ch + (size_t)row * N + col)       = h01;
                    *(uint32_t*)(Cl + (size_t)row * N + col)       = l01;
                    *(uint32_t*)(Ch + (size_t)(row + 8) * N + col) = h23;
                    *(uint32_t*)(Cl + (size_t)(row + 8) * N + col) = l23;
                }
            }
        }
    }
}

// ---------------- helpers ----------------
__device__ __forceinline__ float siluf(float v) { return v / (1.f + expf(-v)); }

__device__ __forceinline__ float blockReduceSum256(float v) {
    __shared__ float s[8];
    __shared__ float tot;
    int lane = threadIdx.x & 31, w = threadIdx.x >> 5;
    #pragma unroll
    for (int o = 16; o; o >>= 1) v += __shfl_xor_sync(0xffffffffu, v, o);
    if (lane == 0) s[w] = v;
    __syncthreads();
    if (threadIdx.x < 32) {
        float t = (threadIdx.x < 8) ? s[threadIdx.x] : 0.f;
        #pragma unroll
        for (int o = 4; o; o >>= 1) t += __shfl_xor_sync(0xffffffffu, t, o);
        if (threadIdx.x == 0) tot = t;
    }
    __syncthreads();
    return tot;
}

// ---------------- elementwise kernels ----------------
__global__ void concat_kernel(const float* __restrict__ x, const float* __restrict__ sl,
                              const float* __restrict__ cr,
                              __nv_bfloat16* __restrict__ oh, __nv_bfloat16* __restrict__ ol)
{
    int idx = blockIdx.x * blockDim.x + threadIdx.x;   // NTOK*512
    int c = idx & 511, r = idx >> 9;
    float v;
    if (c < STATE)      v = x[(size_t)r * STATE + c];
    else if (c == STATE) v = sl[r];
    else                 v = cr[r];
    __nv_bfloat16 h = __float2bfloat16(v);
    oh[idx] = h;
    ol[idx] = __float2bfloat16(v - __bfloat162float(h));
}

__global__ void conv_silu_kernel(const float* __restrict__ zb, const float* __restrict__ cw,
                                 const float* __restrict__ cb, float* __restrict__ out)
{
    int idx = blockIdx.x * blockDim.x + threadIdx.x;   // NTOK*CONV_DIM
    if (idx >= NTOK * CONV_DIM) return;
    int ch = idx % CONV_DIM;
    int t  = idx / CONV_DIM;
    int l = t & (SEQ - 1), b = t >> 9;
    float s = cb[ch];
    #pragma unroll
    for (int k = 0; k < DCONV; k++) {
        int ll = l - (DCONV - 1) + k;
        if (ll >= 0)
            s = fmaf(zb[((size_t)(b * SEQ + ll)) * D_IN_PROJ + D_INNER + ch], cw[ch * DCONV + k], s);
    }
    out[idx] = siluf(s);
}

__global__ void dt_kernel(const float* __restrict__ zb, const float* __restrict__ dtb,
                          const float* __restrict__ Alog,
                          float* __restrict__ dt, float* __restrict__ dA)
{
    int idx = blockIdx.x * blockDim.x + threadIdx.x;   // NTOK*NHEADS
    if (idx >= NTOK * NHEADS) return;
    int hh = idx & (NHEADS - 1), row = idx >> 5;
    float v = zb[(size_t)row * D_IN_PROJ + (D_INNER + CONV_DIM) + hh] + dtb[hh];
    float sp = (v > 20.f) ? v : log1pf(expf(v));
    float a = -expf(Alog[hh]);
    dt[idx] = sp;
    dA[idx] = expf(sp * a);
}

// ---------------- selective scan: 1 CTA per (b, head), 256 threads ----------------
// nq = tid & 15 (8-state slice), pq = tid >> 4 (4 p-values: pq*4..pq*4+3).
// B/C chunk-permuted: chunk c stored at slot (c>>1) + (c&1)*16, so warp loads
// (fixed j, lanes over nq) hit slots j*16+nq -> 2-phase conflict-free.
// Inner math in packed fp32x2 (mul/fma.rn.f32x2) to halve FMA-pipe pressure.
#define SCHUNK 16
#define NCHUNK (SEQ / SCHUNK)

__global__ __launch_bounds__(256)
void scan_kernel(const float* __restrict__ conv, const float* __restrict__ dt,
                 const float* __restrict__ dA, const float* __restrict__ Dsk,
                 float* __restrict__ y)
{
    __shared__ float sB[2][SCHUNK][D_STATE];
    __shared__ float sC[2][SCHUNK][D_STATE];
    __shared__ float sX[2][SCHUNK][HEADDIM];
    __shared__ float sdt[2][SCHUNK];
    __shared__ float sda[2][SCHUNK];

    int bh = blockIdx.x;
    int b = bh >> 5, hh = bh & 31;
    int tid = threadIdx.x;
    int nq = tid & 15, pq = tid >> 4;

    const size_t convb = (size_t)b * SEQ * CONV_DIM;
    const uint32_t sBa = smem_to_u32(&sB[0][0][0]);
    const uint32_t sCa = smem_to_u32(&sC[0][0][0]);
    const uint32_t sXa = smem_to_u32(&sX[0][0][0]);
    const uint32_t sdta = smem_to_u32(&sdt[0][0]);
    const uint32_t sdaa = smem_to_u32(&sda[0][0]);

    auto issue = [&](int ch) {
        const int l0 = ch * SCHUNK;
        const int buf = ch & 1;
        #pragma unroll
        for (int t = 0; t < 2; t++) {   // B: 512 chunks, 2 per thread
            int idx = tid + t * 256;
            int st = idx >> 5, f4 = idx & 31;
            int dstc = (f4 >> 1) + (f4 & 1) * 16;
            const float* src = conv + convb + (size_t)(l0 + st) * CONV_DIM + D_INNER + f4 * 4;
            CP_ASYNC16(sBa + (uint32_t)(buf * SCHUNK * D_STATE + st * D_STATE + dstc * 4) * 4u, src);
        }
        #pragma unroll
        for (int t = 0; t < 2; t++) {   // C
            int idx = tid + t * 256;
            int st = idx >> 5, f4 = idx & 31;
            int dstc = (f4 >> 1) + (f4 & 1) * 16;
            const float* src = conv + convb + (size_t)(l0 + st) * CONV_DIM + D_INNER + D_STATE + f4 * 4;
            CP_ASYNC16(sCa + (uint32_t)(buf * SCHUNK * D_STATE + st * D_STATE + dstc * 4) * 4u, src);
        }
        {   // X: 256 chunks, 1 per thread
            int st = tid >> 4, f4 = tid & 15;
            const float* src = conv + convb + (size_t)(l0 + st) * CONV_DIM + hh * HEADDIM + f4 * 4;
            CP_ASYNC16(sXa + (uint32_t)(buf * SCHUNK * HEADDIM + st * HEADDIM + f4 * 4) * 4u, src);
        }
        if (tid < SCHUNK) {
            CP_ASYNC4(sdta + (uint32_t)(buf * SCHUNK + tid) * 4u,
                      dt + (size_t)(b * SEQ + l0 + tid) * NHEADS + hh);
        } else if (tid < 2 * SCHUNK) {
            int s = tid - SCHUNK;
            CP_ASYNC4(sdaa + (uint32_t)(buf * SCHUNK + s) * 4u,
                      dA + (size_t)(b * SEQ + l0 + s) * NHEADS + hh);
        }
        CP_COMMIT();
    };

    ull hs2[16];   // [p_i][k]: p_i = idx>>2, k = idx&3; states nq*8+2k, nq*8+2k+1
    #pragma unroll
    for (int i = 0; i < 16; i++) hs2[i] = 0ull;
    float dsk = Dsk[hh];

    issue(0);

    for (int ch = 0; ch < NCHUNK; ch++) {
        if (ch + 1 < NCHUNK) { issue(ch + 1); CP_WAIT1(); }
        else                 { CP_WAIT0(); }
        __syncthreads();
        const int buf = ch & 1;

        #pragma unroll 2
        for (int s = 0; s < SCHUNK; s++) {
            int l = ch * SCHUNK + s;
            float dtv = sdt[buf][s];
            float dav = sda[buf][s];
            ull dav2 = pk2(dav, dav);
            float4 xv = *(const float4*)&sX[buf][s][pq * 4];
            ull coef2[4];
            coef2[0] = pk2(dtv * xv.x, dtv * xv.x);
            coef2[1] = pk2(dtv * xv.y, dtv * xv.y);
            coef2[2] = pk2(dtv * xv.z, dtv * xv.z);
            coef2[3] = pk2(dtv * xv.w, dtv * xv.w);

            const ulonglong2* B2 = (const ulonglong2*)&sB[buf][s][0];
            const ulonglong2* C2 = (const ulonglong2*)&sC[buf][s][0];
            ulonglong2 b0 = B2[nq], b1 = B2[16 + nq];   // slots j*16+nq
            ulonglong2 c0 = C2[nq], c1 = C2[16 + nq];
            ull bv2[4] = {b0.x, b0.y, b1.x, b1.y};
            ull cv2[4] = {c0.x, c0.y, c1.x, c1.y};

            ull acc2[4];
            #pragma unroll
            for (int i = 0; i < 4; i++) acc2[i] = 0ull;

            #pragma unroll
            for (int i = 0; i < 4; i++) {
                #pragma unroll
                for (int k = 0; k < 4; k++) {
                    ull t;
                    MUL2(t, coef2[i], bv2[k]);
                    FMA2(hs2[i * 4 + k], hs2[i * 4 + k], dav2, t);
                    FMA2(acc2[i], hs2[i * 4 + k], cv2[k], acc2[i]);
                }
            }

            float acc[4];
            #pragma unroll
            for (int i = 0; i < 4; i++) {
                float lo, hi;
                upk2(acc2[i], lo, hi);
                acc[i] = lo + hi;
                acc[i] += __shfl_xor_sync(0xffffffffu, acc[i], 1);
                acc[i] += __shfl_xor_sync(0xffffffffu, acc[i], 2);
                acc[i] += __shfl_xor_sync(0xffffffffu, acc[i], 4);
                acc[i] += __shfl_xor_sync(0xffffffffu, acc[i], 8);
            }
            if (nq == 0) {
                float4 outv;
                outv.x = acc[0] + dsk * xv.x;
                outv.y = acc[1] + dsk * xv.y;
                outv.z = acc[2] + dsk * xv.z;
                outv.w = acc[3] + dsk * xv.w;
                *(float4*)&y[((size_t)(b * SEQ + l)) * D_INNER + hh * HEADDIM + pq * 4] = outv;
            }
        }
        __syncthreads();
    }
}

// ---------------- gated RMSNorm (writes bf16 hi/lo for next GEMM) ----------------
__global__ __launch_bounds__(256)
void gated_norm_kernel(const float* __restrict__ y, const float* __restrict__ z,
                       const float* __restrict__ nw,
                       __nv_bfloat16* __restrict__ oh, __nv_bfloat16* __restrict__ ol)
{
    int r = blockIdx.x;
    float g[8];
    float ss = 0.f;
    #pragma unroll
    for (int j = 0; j < 8; j++) {
        int c = j * 256 + threadIdx.x;
        float zv = z[(size_t)r * D_IN_PROJ + c];
        float gv = y[(size_t)r * D_INNER + c] * siluf(zv);
        g[j] = gv;
        ss = fmaf(gv, gv, ss);
    }
    ss = blockReduceSum256(ss);
    float inv = rsqrtf(ss / (float)D_INNER + 1e-5f);
    #pragma unroll
    for (int j = 0; j < 8; j++) {
        int c = j * 256 + threadIdx.x;
        float v = g[j] * inv * nw[c];
        __nv_bfloat16 h = __float2bfloat16(v);
        oh[(size_t)r * D_INNER + c] = h;
        ol[(size_t)r * D_INNER + c] = __float2bfloat16(v - __bfloat162float(h));
    }
}

// ---------------- final N=1 projection ----------------
__global__ __launch_bounds__(256)
void dot_kernel(const float* __restrict__ t, const float* __restrict__ w,
                const float* __restrict__ b, float* __restrict__ out)
{
    int r = blockIdx.x;
    float s = 0.f;
    for (int k = threadIdx.x; k < D_MODEL; k += 256)
        s = fmaf(t[(size_t)r * D_MODEL + k], w[k], s);
    s = blockReduceSum256(s);
    if (threadIdx.x == 0) out[r] = s + b[0];
}

// ---------------- launch ----------------
extern "C" void kernel_launch(void* const* d_in, const int* in_sizes, int n_in,
                              void* d_out, int out_size)
{
    const float* x    = (const float*)d_in[0];
    const float* sl   = (const float*)d_in[1];
    const float* cr   = (const float*)d_in[2];
    const float* iw1  = (const float*)d_in[3];
    const float* ib1  = (const float*)d_in[4];
    const float* iw2  = (const float*)d_in[5];
    const float* ib2  = (const float*)d_in[6];
    const float* Win  = (const float*)d_in[7];
    const float* cw   = (const float*)d_in[8];
    const float* cb   = (const float*)d_in[9];
    const float* dtb  = (const float*)d_in[10];
    const float* Alog = (const float*)d_in[11];
    const float* Dsk  = (const float*)d_in[12];
    const float* nw   = (const float*)d_in[13];
    const float* Wout = (const float*)d_in[14];
    const float* ow1  = (const float*)d_in[15];
    const float* ob1  = (const float*)d_in[16];
    const float* ow2  = (const float*)d_in[17];
    const float* ob2  = (const float*)d_in[18];
    float* out = (float*)d_out;

    float *tmp, *h, *z, *conv, *dt, *dA, *y;
    __nv_bfloat16 *cath, *catl, *tmph, *tmpl, *hh_, *hl_, *ynh, *ynl, *wth, *wtl;
    cudaGetSymbolAddress((void**)&tmp,  g_tmp);
    cudaGetSymbolAddress((void**)&h,    g_h);
    cudaGetSymbolAddress((void**)&z,    g_z);
    cudaGetSymbolAddress((void**)&conv, g_conv);
    cudaGetSymbolAddress((void**)&dt,   g_dt);
    cudaGetSymbolAddress((void**)&dA,   g_dA);
    cudaGetSymbolAddress((void**)&y,    g_y);
    cudaGetSymbolAddress((void**)&cath, g_cat_h);
    cudaGetSymbolAddress((void**)&catl, g_cat_l);
    cudaGetSymbolAddress((void**)&tmph, g_tmp_h);
    cudaGetSymbolAddress((void**)&tmpl, g_tmp_l);
    cudaGetSymbolAddress((void**)&hh_,  g_h_h);
    cudaGetSymbolAddress((void**)&hl_,  g_h_l);
    cudaGetSymbolAddress((void**)&ynh,  g_yn_h);
    cudaGetSymbolAddress((void**)&ynl,  g_yn_l);
    cudaGetSymbolAddress((void**)&wth,  g_wth);
    cudaGetSymbolAddress((void**)&wtl,  g_wtl);

    cudaFuncSetAttribute(gemm_bf3<1,1,1>, cudaFuncAttributeMaxDynamicSharedMemorySize, GEMM_SMEM_BYTES);
    cudaFuncSetAttribute(gemm_bf3<1,0,1>, cudaFuncAttributeMaxDynamicSharedMemorySize, GEMM_SMEM_BYTES);
    cudaFuncSetAttribute(gemm_bf3<0,0,0>, cudaFuncAttributeMaxDynamicSharedMemorySize, GEMM_SMEM_BYTES);
    cudaFuncSetAttribute(gemm_bf3<0,0,1>, cudaFuncAttributeMaxDynamicSharedMemorySize, GEMM_SMEM_BYTES);
    cudaFuncSetAttribute(gemm_bf3<1,1,0>, cudaFuncAttributeMaxDynamicSharedMemorySize, GEMM_SMEM_BYTES);

    const int MT = NTOK / 128;   // 16 M-tiles
    dim3 wsb(32, 8);

    // ---- input MLP (wsplits hoisted so launch index 3 = gemm_bf3 for ncu) ----
    wsplit_t<<<dim3(512/32, 512/32), wsb>>>(iw1, wth, wtl, 512, 512);                 // 0
    __nv_bfloat16* wth2 = wth + (size_t)512 * 512;
    __nv_bfloat16* wtl2 = wtl + (size_t)512 * 512;
    wsplit_t<<<dim3(D_MODEL/32, 512/32), wsb>>>(iw2, wth2, wtl2, 512, D_MODEL);       // 1
    concat_kernel<<<NTOK * 512 / 256, 256>>>(x, sl, cr, cath, catl);                  // 2
    gemm_bf3<1,1,1><<<dim3(512/128, MT), 256, GEMM_SMEM_BYTES>>>(                     // 3 <- profiled
        cath, catl, wth, wtl, ib1, tmp, tmph, tmpl, NTOK, 512, 512);
    gemm_bf3<1,0,1><<<dim3(D_MODEL/128, MT), 256, GEMM_SMEM_BYTES>>>(
        tmph, tmpl, wth2, wtl2, ib2, h, hh_, hl_, NTOK, D_MODEL, 512);

    for (int i = 0; i < NBLOCKS; i++) {
        wsplit_t<<<dim3(D_IN_PROJ/32, D_MODEL/32), wsb>>>(
            Win + (size_t)i * D_MODEL * D_IN_PROJ, wth, wtl, D_MODEL, D_IN_PROJ);
        gemm_bf3<0,0,0><<<dim3((D_IN_PROJ + 127)/128, MT), 256, GEMM_SMEM_BYTES>>>(
            hh_, hl_, wth, wtl, nullptr, z, nullptr, nullptr, NTOK, D_IN_PROJ, D_MODEL);
        conv_silu_kernel<<<(NTOK * CONV_DIM + 255) / 256, 256>>>(
            z, cw + (size_t)i * CONV_DIM * DCONV, cb + (size_t)i * CONV_DIM, conv);
        dt_kernel<<<(NTOK * NHEADS) / 256, 256>>>(
            z, dtb + i * NHEADS, Alog + i * NHEADS, dt, dA);
        scan_kernel<<<BATCH * NHEADS, 256>>>(conv, dt, dA, Dsk + i * NHEADS, y);
        gated_norm_kernel<<<NTOK, 256>>>(y, z, nw + (size_t)i * D_INNER, ynh, ynl);
        wsplit_t<<<dim3(D_MODEL/32, D_INNER/32), wsb>>>(
            Wout + (size_t)i * D_INNER * D_MODEL, wth, wtl, D_INNER, D_MODEL);
        gemm_bf3<0,0,1><<<dim3(D_MODEL/128, MT), 256, GEMM_SMEM_BYTES>>>(
            ynh, ynl, wth, wtl, nullptr, h, hh_, hl_, NTOK, D_MODEL, D_INNER);
    }

    // ---- output MLP ----
    wsplit_t<<<dim3(D_MODEL/32, D_MODEL/32), wsb>>>(ow1, wth, wtl, D_MODEL, D_MODEL);
    gemm_bf3<1,1,0><<<dim3(D_MODEL/128, MT), 256, GEMM_SMEM_BYTES>>>(
        hh_, hl_, wth, wtl, ob1, tmp, nullptr, nullptr, NTOK, D_MODEL, D_MODEL);
    dot_kernel<<<NTOK, 256>>>(tmp, ow2, ob2, out);
}